// round 17
// baseline (speedup 1.0000x reference)
#include <cuda_runtime.h>
#include <cuda_bf16.h>
#include <cstdint>

#define BATCH  64
#define TSTEPS 2048
#define M_ROWS (BATCH * TSTEPS)   // 131072
#define HID    64
#define G4     256
#define NGEMM  20                 // gemm CTAs (SMs 128..147)

typedef unsigned long long ull;

// ---------------------------------------------------------------------------
// Scratch
// ---------------------------------------------------------------------------
__device__ float    g_xg1[(size_t)M_ROWS * G4];   // layer1 preacts, natural layout
__device__ float    g_xg2[(size_t)M_ROWS * G4];   // layer2 preacts, natural layout
__device__ uint4    g_wf1[32 * 8 * 32];           // W_ih1 fragment-ordered (hi+lo)
__device__ unsigned g_flag[BATCH];                // xg2 rows ready per sequence
__device__ unsigned g_flag1[BATCH];               // xg1 rows ready per sequence

// ---------------------------------------------------------------------------
// Helpers
// ---------------------------------------------------------------------------
__device__ __forceinline__ uint32_t packbf(float lo, float hi) {
    uint32_t r;
    asm("cvt.rn.bf16x2.f32 %0, %1, %2;" : "=r"(r) : "f"(hi), "f"(lo));
    return r;
}
__device__ __forceinline__ ull pack64(float lo, float hi) {
    ull r; asm("mov.b64 %0, {%1, %2};" : "=l"(r) : "f"(lo), "f"(hi)); return r;
}
__device__ __forceinline__ void unpack64(ull v, float& lo, float& hi) {
    asm("mov.b64 {%0, %1}, %2;" : "=f"(lo), "=f"(hi) : "l"(v));
}
__device__ __forceinline__ void fma2(ull& acc, ull a, ull b) {
    asm("fma.rn.f32x2 %0, %1, %2, %0;" : "+l"(acc) : "l"(a), "l"(b));
}
__device__ __forceinline__ ull add2(ull a, ull b) {
    ull r; asm("add.rn.f32x2 %0, %1, %2;" : "=l"(r) : "l"(a), "l"(b)); return r;
}
__device__ __forceinline__ float bf16_round(float f) {
    return __bfloat162float(__float2bfloat16_rn(f));
}
__device__ __forceinline__ float tanh_mufu(float x) {
    float y; asm("tanh.approx.f32 %0, %1;" : "=f"(y) : "f"(x)); return y;
}
__device__ __forceinline__ float sig_mufu(float x) {
    return fmaf(tanh_mufu(x * 0.5f), 0.5f, 0.5f);
}
__device__ __forceinline__ void mma16816(float* c, const uint32_t* a,
                                         uint32_t b0, uint32_t b1) {
    asm("mma.sync.aligned.m16n8k16.row.col.f32.bf16.bf16.f32 "
        "{%0,%1,%2,%3}, {%4,%5,%6,%7}, {%8,%9}, {%0,%1,%2,%3};"
        : "+f"(c[0]), "+f"(c[1]), "+f"(c[2]), "+f"(c[3])
        : "r"(a[0]), "r"(a[1]), "r"(a[2]), "r"(a[3]), "r"(b0), "r"(b1));
}
__device__ __forceinline__ unsigned ld_acq(const unsigned* p) {
    unsigned v;
    asm volatile("ld.acquire.gpu.global.u32 %0, [%1];" : "=r"(v) : "l"(p) : "memory");
    return v;
}
__device__ __forceinline__ void st_rel(unsigned* p, unsigned v) {
    asm volatile("st.release.gpu.global.u32 [%0], %1;" :: "l"(p), "r"(v) : "memory");
}
__device__ __forceinline__ void bar_rec256() {       // rec-warps-only barrier
    asm volatile("bar.sync 1, 256;" ::: "memory");
}

// 32-FFMA2 packed dot over h[64] (float smem row), software-pipelined LDS.128.
__device__ __forceinline__ float dot32p(const float* hp_, const ull* wv) {
    const ulonglong2* hp = (const ulonglong2*)hp_;   // 16 entries
    ulonglong2 bufA[4], bufB[4];
#pragma unroll
    for (int i = 0; i < 4; i++) bufA[i] = hp[i];
    ull a0 = 0ull, a1 = 0ull, a2 = 0ull, a3 = 0ull;
#pragma unroll
    for (int c = 0; c < 4; c++) {
        ulonglong2* cur = (c & 1) ? bufB : bufA;
        ulonglong2* nxt = (c & 1) ? bufA : bufB;
        if (c < 3) {
#pragma unroll
            for (int i = 0; i < 4; i++) nxt[i] = hp[(c + 1) * 4 + i];
        }
        fma2(a0, cur[0].x, wv[c * 8 + 0]);
        fma2(a1, cur[0].y, wv[c * 8 + 1]);
        fma2(a2, cur[1].x, wv[c * 8 + 2]);
        fma2(a3, cur[1].y, wv[c * 8 + 3]);
        fma2(a0, cur[2].x, wv[c * 8 + 4]);
        fma2(a1, cur[2].y, wv[c * 8 + 5]);
        fma2(a2, cur[3].x, wv[c * 8 + 6]);
        fma2(a3, cur[3].y, wv[c * 8 + 7]);
    }
    ull s = add2(add2(a0, a1), add2(a2, a3));
    float lo, hi; unpack64(s, lo, hi);
    return lo + hi;
}

// ---------------------------------------------------------------------------
// Prep: W_ih1 fragments + flag reset
// ---------------------------------------------------------------------------
__global__ void prep_w_kernel(const float* __restrict__ W) {
    const int KI = 8, K = 128;
    int total = 32 * KI * 32;
    int i = blockIdx.x * blockDim.x + threadIdx.x;
    if (i < BATCH) { g_flag[i] = 0; g_flag1[i] = 0; }
    if (i >= total) return;
    int lane = i & 31;
    int ki   = (i >> 5) % KI;
    int nt   = i / (32 * KI);
    int tig = lane & 3, gid = lane >> 2;
    int n  = nt * 8 + gid;
    int k0 = ki * 16 + tig * 2;
    const float* Wn = W + (size_t)n * K;
    float w00 = Wn[k0],     w01 = Wn[k0 + 1];
    float w10 = Wn[k0 + 8], w11 = Wn[k0 + 9];
    uint4 v;
    v.x = packbf(w00, w01);
    v.y = packbf(w10, w11);
    v.z = packbf(w00 - bf16_round(w00), w01 - bf16_round(w01));
    v.w = packbf(w10 - bf16_round(w10), w11 - bf16_round(w11));
    g_wf1[(nt * KI + ki) * 32 + lane] = v;
}

// ---------------------------------------------------------------------------
// Mega kernel: 148 CTAs x 512 threads, single wave, three roles.
//  bid <  64 : PRODUCER  (GEMV warps 0-7 LOW priority, layer1 rec warps 8-15
//              HIGH priority — hi-wid-first arbiter), xg1 gated on g_flag1
//              polled once per 16 steps.
//  bid < 128 : CONSUMER  (layer2 rec warps 0-7), xg2 gated on g_flag polled
//              once per 16 steps.
//  bid >=128 : GEMM      (xg1 tiles, 16 warps, in-register bf16 packing)
// ---------------------------------------------------------------------------
__global__ __launch_bounds__(512, 1) void mega_kernel(
    const float* __restrict__ x,
    const float* __restrict__ Whh1, const float* __restrict__ mask1,
    const float* __restrict__ Wih2, const float* __restrict__ bih2,
    const float* __restrict__ bhh2,
    const float* __restrict__ Whh2, const float* __restrict__ mask2,
    const float* __restrict__ bih1, const float* __restrict__ bhh1,
    float* __restrict__ out)
{
    __shared__ alignas(16) float ring[8][64];   // h history: row t at ring[t&7]

    int tid = threadIdx.x;
    int bid = blockIdx.x;
    int lane = tid & 31, w = tid >> 5;

    if (bid >= 2 * BATCH) {
        // ==================== GEMM role: xg1 tiles ====================
        int j = bid - 2 * BATCH;                            // 0..NGEMM-1
        int wm = w & 3, wn = w >> 2;                        // 4 m-slices x 4 n-quarters
        int tig = lane & 3, gid = lane >> 2;
        for (int tc = 0; tc < TSTEPS / 64; tc++) {
            for (int b = j; b < BATCH; b += NGEMM) {
                size_t rowbase = (size_t)b * TSTEPS + tc * 64 + wm * 16 + gid;
                float acc[8][4];
#pragma unroll
                for (int jl = 0; jl < 8; jl++)
#pragma unroll
                    for (int q = 0; q < 4; q++) acc[jl][q] = 0.0f;
#pragma unroll
                for (int ki = 0; ki < 8; ki++) {
                    const float* xr = x + rowbase * 128 + ki * 16 + tig * 2;
                    float2 v0 = *(const float2*)(xr);
                    float2 v1 = *(const float2*)(xr + 8 * 128);
                    float2 v2 = *(const float2*)(xr + 8);
                    float2 v3 = *(const float2*)(xr + 8 * 128 + 8);
                    uint32_t a[4], al[4];
                    a[0]  = packbf(v0.x, v0.y);
                    a[1]  = packbf(v1.x, v1.y);
                    a[2]  = packbf(v2.x, v2.y);
                    a[3]  = packbf(v3.x, v3.y);
                    al[0] = packbf(v0.x - bf16_round(v0.x), v0.y - bf16_round(v0.y));
                    al[1] = packbf(v1.x - bf16_round(v1.x), v1.y - bf16_round(v1.y));
                    al[2] = packbf(v2.x - bf16_round(v2.x), v2.y - bf16_round(v2.y));
                    al[3] = packbf(v3.x - bf16_round(v3.x), v3.y - bf16_round(v3.y));
#pragma unroll
                    for (int jl = 0; jl < 8; jl++) {
                        uint4 bf = __ldg(&g_wf1[((wn * 8 + jl) * 8 + ki) * 32 + lane]);
                        mma16816(acc[jl], a,  bf.x, bf.y);
                        mma16816(acc[jl], a,  bf.z, bf.w);
                        mma16816(acc[jl], al, bf.x, bf.y);
                    }
                }
#pragma unroll
                for (int jl = 0; jl < 8; jl++) {
                    int nc = (wn * 8 + jl) * 8 + tig * 2;
                    float bs0 = __ldg(bih1 + nc) + __ldg(bhh1 + nc);
                    float bs1 = __ldg(bih1 + nc + 1) + __ldg(bhh1 + nc + 1);
                    *(float2*)(g_xg1 + rowbase * G4 + nc) =
                        make_float2(acc[jl][0] + bs0, acc[jl][1] + bs1);
                    *(float2*)(g_xg1 + (rowbase + 8) * G4 + nc) =
                        make_float2(acc[jl][2] + bs0, acc[jl][3] + bs1);
                }
                __syncthreads();                            // tile stores done
                if (tid == 0) {
                    __threadfence();
                    st_rel(&g_flag1[b], (unsigned)((tc + 1) * 64));
                }
            }
        }
        return;
    }

    bool producer = bid < BATCH;
    int b = producer ? bid : bid - BATCH;

    if (producer) {
        if (w >= 8) {
            // ==== layer1 rec: warps 8-15 (HIGH arbiter priority) ====
            int ti = tid - 256;                             // 0..255
            int wr = w - 8;
            int gt = lane >> 3;
            int u  = (wr << 3) + (lane & 7);
            int gidx = gt * 64 + u;
            ull wv[32];
#pragma unroll
            for (int k = 0; k < 32; k++)
                wv[k] = pack64(__ldg(Whh1 + (size_t)gidx * 64 + 2 * k),
                               __ldg(Whh1 + (size_t)gidx * 64 + 2 * k + 1));
            if (ti < 64) ring[7][ti] = 0.0f;                // h(-1) = 0
            float c = 0.0f;
            const float* xgp = g_xg1 + (size_t)b * TSTEPS * G4 + gidx;
            unsigned avail1 = 0;
            bar_rec256();                                   // ring init visible
            while (avail1 < 4u) { avail1 = ld_acq(&g_flag1[b]); if (avail1 < 4u) __nanosleep(64); }
            float xr[4];
#pragma unroll
            for (int p = 0; p < 4; p++) xr[p] = xgp[(size_t)p * G4];  // PLAIN
            for (int t0 = 0; t0 < TSTEPS; t0 += 4) {
                if ((t0 & 15) == 0 && t0 + 4 < TSTEPS) {    // poll 1x / 16 steps
                    unsigned need = (unsigned)(t0 + 20 > TSTEPS ? TSTEPS : t0 + 20);
                    while (avail1 < need) { avail1 = ld_acq(&g_flag1[b]); if (avail1 < need) __nanosleep(64); }
                }
#pragma unroll
                for (int p = 0; p < 4; p++) {
                    int t = t0 + p;
                    float xc = xr[p];
                    if (t + 4 < TSTEPS)
                        xr[p] = xgp[(size_t)(t + 4) * G4];  // PLAIN load
                    float pre = dot32p(ring[(t + 7) & 7], wv) + xc;
                    float A = (gt == 2) ? tanh_mufu(pre) : sig_mufu(pre);
                    float fA = __shfl_xor_sync(0xffffffffu, A, 8);
                    float gA = __shfl_xor_sync(0xffffffffu, A, 16);
                    float oA = __shfl_xor_sync(0xffffffffu, A, 24);
                    if (lane < 8) {                         // i-lanes own unit u
                        c = fA * c + A * gA;
                        float h = oA * tanh_mufu(c);
                        ring[t & 7][u] = h;
                    }
                    bar_rec256();                           // rec-only, per step
                }
                __syncthreads();                            // joint, every 4
            }
            __syncthreads();                                // final joint
        } else {
            // ==== GEMV: warps 0-7 (LOW arbiter priority) ====
            int s = tid;                                    // gate 0..255
            ull wv2[32];
#pragma unroll
            for (int k = 0; k < 32; k++) {
                float m0 = __ldg(mask1 + b * 64 + 2 * k);
                float m1 = __ldg(mask1 + b * 64 + 2 * k + 1);
                wv2[k] = pack64(__ldg(Wih2 + (size_t)s * 64 + 2 * k) * m0,
                                __ldg(Wih2 + (size_t)s * 64 + 2 * k + 1) * m1);
            }
            float bias = __ldg(bih2 + s) + __ldg(bhh2 + s);
            float* dst = g_xg2 + (size_t)b * TSTEPS * G4 + s;
            for (int kk = 1; kk <= TSTEPS / 4; kk++) {
                __syncthreads();                            // joint barrier kk
                int r0 = 4 * (kk - 1);
                if (tid == 0 && r0 > 0) {
                    __threadfence();
                    st_rel(&g_flag[b], (unsigned)r0);       // rows 0..r0-1 ready
                }
#pragma unroll
                for (int jl = 0; jl < 4; jl++)
                    dst[(size_t)(r0 + jl) * G4] = dot32p(ring[(r0 + jl) & 7], wv2) + bias;
            }
            __syncthreads();                                // final joint
            if (tid == 0) {
                __threadfence();
                st_rel(&g_flag[b], (unsigned)TSTEPS);
            }
        }
    } else {
        // ======== consumer: layer2 recurrence, 1 gate/thread ========
        if (w >= 8) return;                                 // warps 8-15 exit
        int gt = lane >> 3;
        int u  = (w << 3) + (lane & 7);
        int gidx = gt * 64 + u;
        ull wv[32];
#pragma unroll
        for (int k = 0; k < 32; k++)
            wv[k] = pack64(__ldg(Whh2 + (size_t)gidx * 64 + 2 * k),
                           __ldg(Whh2 + (size_t)gidx * 64 + 2 * k + 1));
        float mval = (lane < 8) ? __ldg(mask2 + b * 64 + u) : 0.0f;
        if (tid < 64) ring[7][tid] = 0.0f;
        float c = 0.0f;
        const float* xgp = g_xg2 + (size_t)b * TSTEPS * G4 + gidx;
        unsigned avail = 0;
        bar_rec256();
        while (avail < 4u) { avail = ld_acq(&g_flag[b]); if (avail < 4u) __nanosleep(64); }
        float xr[4];
#pragma unroll
        for (int p = 0; p < 4; p++) xr[p] = xgp[(size_t)p * G4];   // PLAIN
        for (int t0 = 0; t0 < TSTEPS; t0 += 4) {
            if ((t0 & 15) == 0 && t0 + 4 < TSTEPS) {        // poll 1x / 16 steps
                unsigned need = (unsigned)(t0 + 20 > TSTEPS ? TSTEPS : t0 + 20);
                while (avail < need) { avail = ld_acq(&g_flag[b]); if (avail < need) __nanosleep(64); }
            }
#pragma unroll
            for (int p = 0; p < 4; p++) {
                int t = t0 + p;
                float xc = xr[p];
                if (t + 4 < TSTEPS)
                    xr[p] = xgp[(size_t)(t + 4) * G4];      // PLAIN load
                float pre = dot32p(ring[(t + 7) & 7], wv) + xc;
                float A = (gt == 2) ? tanh_mufu(pre) : sig_mufu(pre);
                float fA = __shfl_xor_sync(0xffffffffu, A, 8);
                float gA = __shfl_xor_sync(0xffffffffu, A, 16);
                float oA = __shfl_xor_sync(0xffffffffu, A, 24);
                if (lane < 8) {
                    c = fA * c + A * gA;
                    float h = oA * tanh_mufu(c);
                    ring[t & 7][u] = h;
                    out[((size_t)b * TSTEPS + t) * HID + u] = fmaxf(h * mval, 0.0f);
                }
                bar_rec256();
            }
        }
    }
}

// ---------------------------------------------------------------------------
// Launch
// ---------------------------------------------------------------------------
extern "C" void kernel_launch(void* const* d_in, const int* in_sizes, int n_in,
                              void* d_out, int out_size) {
    const float* x     = (const float*)d_in[0];
    const float* W_ih1 = (const float*)d_in[1];
    const float* W_hh1 = (const float*)d_in[2];
    const float* b_ih1 = (const float*)d_in[3];
    const float* b_hh1 = (const float*)d_in[4];
    const float* W_ih2 = (const float*)d_in[5];
    const float* W_hh2 = (const float*)d_in[6];
    const float* b_ih2 = (const float*)d_in[7];
    const float* b_hh2 = (const float*)d_in[8];
    const float* mask1 = (const float*)d_in[9];
    const float* mask2 = (const float*)d_in[10];
    float* out = (float*)d_out;

    prep_w_kernel<<<64, 128>>>(W_ih1);
    mega_kernel<<<2 * BATCH + NGEMM, 512>>>(x, W_hh1, mask1, W_ih2, b_ih2,
                                            b_hh2, W_hh2, mask2, b_ih1, b_hh1,
                                            out);
}